// round 6
// baseline (speedup 1.0000x reference)
#include <cuda_runtime.h>
#include <cuda_fp16.h>
#include <cstdint>

// ---------------- problem constants ----------------
#define B   512
#define NN  21
#define II  256
#define HH  1024
#define FH  4096          // 4*HH
#define KK  1280          // II + HH
#define EPS 1e-12f

// ---------------- GEMM tiling ----------------
#define TM 128            // batch rows per CTA
#define TN 256            // out cols per CTA
#define TK 32             // K halves per stage (64 bytes)
#define NSTAGE 4
#define NCHUNK (KK / TK)  // 40
#define KGROUP 4          // promote fp16 acc -> fp32 every 4 k-tiles (K=128)
#define PADB 80           // bytes per smem row (64 + 16 pad -> conflict-free ldmatrix)

#define A_STAGE_B (TM * PADB)      // 10240 bytes
#define B_STAGE_B (TN * PADB)      // 20480 bytes
#define STAGE_B   (A_STAGE_B + B_STAGE_B)
#define SM_BYTES  (NSTAGE * STAGE_B)   // 122880

// ---------------- scratch (__device__ globals; no allocation) ----------------
__device__ float  g_gates[(size_t)B * NN * FH];    // [B][NN][4H] pre-mix gates
__device__ float  g_gx[NN * NN];                   // row-L1-normalized G
__device__ __half g_wih_h[(size_t)5 * FH * II];    // fp16 weights
__device__ __half g_whh_h[(size_t)5 * FH * HH];
__device__ __half g_in_h[(size_t)B * NN * II];     // fp16 input
__device__ __half g_hx_h[(size_t)B * NN * HH];     // fp16 hx

// ---------------- helpers ----------------
__device__ __forceinline__ uint32_t smem_u32(const void* p) {
    uint32_t a;
    asm("{ .reg .u64 t; cvta.to.shared.u64 t, %1; cvt.u32.u64 %0, t; }" : "=r"(a) : "l"(p));
    return a;
}
__device__ __forceinline__ void cp16(uint32_t saddr, const void* gptr) {
    asm volatile("cp.async.cg.shared.global [%0], [%1], 16;" :: "r"(saddr), "l"(gptr));
}
__device__ __forceinline__ void ldsm4(uint32_t* r, uint32_t saddr) {
    asm volatile("ldmatrix.sync.aligned.m8n8.x4.shared.b16 {%0,%1,%2,%3}, [%4];"
                 : "=r"(r[0]), "=r"(r[1]), "=r"(r[2]), "=r"(r[3]) : "r"(saddr));
}
// fp16 accumulator MMA: d,c are 2x b32 (4 halves), same (row,col) slots as f32 quad
__device__ __forceinline__ void mma16h(uint32_t* c, const uint32_t* a, const uint32_t* b) {
    asm volatile(
        "mma.sync.aligned.m16n8k16.row.col.f16.f16.f16.f16 "
        "{%0,%1}, {%2,%3,%4,%5}, {%6,%7}, {%0,%1};"
        : "+r"(c[0]), "+r"(c[1])
        : "r"(a[0]), "r"(a[1]), "r"(a[2]), "r"(a[3]), "r"(b[0]), "r"(b[1]));
}

// ---------------- kernel: fp32 -> fp16 conversion (8 elems/thread) ----------------
__global__ void cvt_h_kernel(const float4* __restrict__ src, uint4* __restrict__ dst, int n8) {
    int i = blockIdx.x * blockDim.x + threadIdx.x;
    if (i < n8) {
        float4 v0 = src[2 * i];
        float4 v1 = src[2 * i + 1];
        __half2 h0 = __floats2half2_rn(v0.x, v0.y);
        __half2 h1 = __floats2half2_rn(v0.z, v0.w);
        __half2 h2 = __floats2half2_rn(v1.x, v1.y);
        __half2 h3 = __floats2half2_rn(v1.z, v1.w);
        uint4 o;
        o.x = *(uint32_t*)&h0; o.y = *(uint32_t*)&h1;
        o.z = *(uint32_t*)&h2; o.w = *(uint32_t*)&h3;
        dst[i] = o;
    }
}

// ---------------- kernel 0: gx normalization ----------------
__global__ void gx_kernel(const float* __restrict__ G, float* __restrict__ gx_out) {
    __shared__ float sG[NN * NN];
    __shared__ float den[NN];
    __shared__ float den2[NN];
    int tid = threadIdx.x;
    for (int i = tid; i < NN * NN; i += blockDim.x) sG[i] = G[i];
    __syncthreads();
    if (tid < NN) {
        float s = 0.f;
        for (int j = 0; j < NN; j++) s += fabsf(sG[tid * NN + j]);
        den[tid] = fmaxf(s, EPS);
    }
    __syncthreads();
    for (int i = tid; i < NN * NN; i += blockDim.x) sG[i] = sG[i] / den[i / NN];
    __syncthreads();
    if (tid < NN) {
        float s = 0.f;
        for (int j = 0; j < NN; j++) s += fabsf(sG[tid * NN + j]);
        den2[tid] = fmaxf(s, EPS);
    }
    __syncthreads();
    for (int i = tid; i < NN * NN; i += blockDim.x) {
        g_gx[i]   = sG[i];
        gx_out[i] = sG[i] / den2[i / NN];
    }
}

// ---------------- kernel 1: fp16 mma.sync gates GEMM (fp16 acc + fp32 promote) ----------------
__global__ __launch_bounds__(256, 1)
void gates_gemm(const float* __restrict__ bhh, const int* __restrict__ ntypes) {
    extern __shared__ char smc[];
    const int tid  = threadIdx.x;
    const int lane = tid & 31;
    const int wid  = tid >> 5;

    const int n  = blockIdx.z;
    const int bm = blockIdx.y * TM;
    const int bo = blockIdx.x * TN;
    const int nt = ntypes[n];
    const __half* wih = g_wih_h + (size_t)nt * FH * II;
    const __half* whh = g_whh_h + (size_t)nt * FH * HH;

    const uint32_t sb = smem_u32(smc);

    // warp tiling: 2 (m) x 4 (n), warp tile 64x64
    const int wm = (wid & 1) * 64;
    const int wn = (wid >> 1) * 64;

    // ldmatrix lane byte offsets (validated in round 5)
    const uint32_t aL = (uint32_t)((((lane >> 3) & 1) * 8 + (lane & 7)) * PADB + (lane >> 4) * 16);
    const uint32_t bL = (uint32_t)((((lane >> 4) & 1) * 8 + (lane & 7)) * PADB + ((lane >> 3) & 1) * 16);

    float acc[4][8][4];
#pragma unroll
    for (int i = 0; i < 4; i++)
#pragma unroll
        for (int j = 0; j < 8; j++)
#pragma unroll
            for (int v = 0; v < 4; v++) acc[i][j][v] = 0.f;

    uint32_t acch[4][8][2];   // fp16 group accumulators

    // ---- stage loader ----
    auto load_stage = [&](int kt) {
        const int s  = kt % NSTAGE;
        const int k0 = kt * TK;
        const uint32_t ab = sb + (uint32_t)(s * STAGE_B);
        const uint32_t bb = ab + (uint32_t)A_STAGE_B;
#pragma unroll
        for (int i = 0; i < 2; i++) {
            int f = tid + i * 256;
            int r = f >> 2, c = f & 3;
            int k = k0 + c * 8;
            const __half* src = (k < II)
                ? g_in_h + ((size_t)(bm + r) * NN + n) * II + k
                : g_hx_h + ((size_t)(bm + r) * NN + n) * HH + (k - II);
            cp16(ab + (uint32_t)(r * PADB + c * 16), src);
        }
#pragma unroll
        for (int i = 0; i < 4; i++) {
            int f = tid + i * 256;
            int r = f >> 2, c = f & 3;
            int k = k0 + c * 8;
            const __half* src = (k < II)
                ? wih + (size_t)(bo + r) * II + k
                : whh + (size_t)(bo + r) * HH + (k - II);
            cp16(bb + (uint32_t)(r * PADB + c * 16), src);
        }
    };

    // prologue
#pragma unroll
    for (int s = 0; s < NSTAGE; s++) {
        load_stage(s);
        asm volatile("cp.async.commit_group;" ::: "memory");
    }

    // mainloop
    for (int kt = 0; kt < NCHUNK; kt++) {
        asm volatile("cp.async.wait_group %0;" :: "n"(NSTAGE - 1) : "memory");
        __syncthreads();

        if ((kt & (KGROUP - 1)) == 0) {
#pragma unroll
            for (int mi = 0; mi < 4; mi++)
#pragma unroll
                for (int ni = 0; ni < 8; ni++) {
                    acch[mi][ni][0] = 0u;
                    acch[mi][ni][1] = 0u;
                }
        }

        const int s = kt % NSTAGE;
        const uint32_t sAb = sb + (uint32_t)(s * STAGE_B);
        const uint32_t sBb = sAb + (uint32_t)A_STAGE_B;

#pragma unroll
        for (int ks = 0; ks < TK / 16; ks++) {
            const uint32_t kb = (uint32_t)(ks * 32);
            uint32_t af[4][4];
#pragma unroll
            for (int mi = 0; mi < 4; mi++)
                ldsm4(af[mi], sAb + (uint32_t)((wm + mi * 16) * PADB) + kb + aL);
            uint32_t bq[4][4];
#pragma unroll
            for (int np = 0; np < 4; np++)
                ldsm4(bq[np], sBb + (uint32_t)((wn + np * 16) * PADB) + kb + bL);
#pragma unroll
            for (int mi = 0; mi < 4; mi++)
#pragma unroll
                for (int ni = 0; ni < 8; ni++)
                    mma16h(acch[mi][ni], af[mi], &bq[ni >> 1][(ni & 1) * 2]);
        }

        if ((kt & (KGROUP - 1)) == (KGROUP - 1)) {
            // promote fp16 group sums into fp32 accumulators
#pragma unroll
            for (int mi = 0; mi < 4; mi++)
#pragma unroll
                for (int ni = 0; ni < 8; ni++) {
                    float2 f0 = __half22float2(*(__half2*)&acch[mi][ni][0]);
                    float2 f1 = __half22float2(*(__half2*)&acch[mi][ni][1]);
                    acc[mi][ni][0] += f0.x;
                    acc[mi][ni][1] += f0.y;
                    acc[mi][ni][2] += f1.x;
                    acc[mi][ni][3] += f1.y;
                }
        }

        __syncthreads();
        if (kt + NSTAGE < NCHUNK) load_stage(kt + NSTAGE);
        asm volatile("cp.async.commit_group;" ::: "memory");
    }

    // ---- epilogue: bias + store (mapping validated in rounds 3-5) ----
    const int lr = lane >> 2;
    const int lq = lane & 3;
    const float* brow = bhh + (size_t)nt * FH + bo;
#pragma unroll
    for (int mi = 0; mi < 4; mi++) {
        int r0 = wm + mi * 16 + lr;
        float* out0 = g_gates + ((size_t)(bm + r0)     * NN + n) * FH + bo;
        float* out1 = g_gates + ((size_t)(bm + r0 + 8) * NN + n) * FH + bo;
#pragma unroll
        for (int ni = 0; ni < 8; ni++) {
            int col = wn + ni * 8 + lq * 2;
            float2 bv = *(const float2*)(brow + col);
            float2 v0 = make_float2(acc[mi][ni][0] + bv.x, acc[mi][ni][1] + bv.y);
            float2 v1 = make_float2(acc[mi][ni][2] + bv.x, acc[mi][ni][3] + bv.y);
            *(float2*)(out0 + col) = v0;
            *(float2*)(out1 + col) = v1;
        }
    }
}

// ---------------- kernel 2: graph mix over n + LSTM epilogue ----------------
__global__ __launch_bounds__(128)
void pass2(const float* __restrict__ cx, const int* __restrict__ tptr,
           float* __restrict__ hy, float* __restrict__ cyo) {
    __shared__ float sgx[NN * NN];
    const int tid = threadIdx.x;
    for (int i = tid; i < NN * NN; i += 128) sgx[i] = g_gx[i];
    __syncthreads();

    const int b = blockIdx.y;
    const int h = blockIdx.x * 128 + tid;

    const float t1    = (float)(*tptr) + 1.0f;
    const float phase = floorf((float)h / (float)(HH - 1) * 8.0f + 1.0f);
    const float mask  = (fmodf(t1, phase) < 0.01f) ? 1.0f : 0.0f;

    float rg0[NN], rg1[NN], rg2[NN], rg3[NN];
    const float* gbase = g_gates + (size_t)b * NN * FH + h;
#pragma unroll
    for (int nI = 0; nI < NN; nI++) {
        rg0[nI] = gbase[(size_t)nI * FH];
        rg1[nI] = gbase[(size_t)nI * FH + HH];
        rg2[nI] = gbase[(size_t)nI * FH + 2 * HH];
        rg3[nI] = gbase[(size_t)nI * FH + 3 * HH];
    }

#pragma unroll 1
    for (int m = 0; m < NN; m++) {
        float ig = 0.f, fg = 0.f, cg = 0.f, og = 0.f;
#pragma unroll
        for (int nI = 0; nI < NN; nI++) {
            float w = sgx[m * NN + nI];
            ig = fmaf(w, rg0[nI], ig);
            fg = fmaf(w, rg1[nI], fg);
            cg = fmaf(w, rg2[nI], cg);
            og = fmaf(w, rg3[nI], og);
        }
        float is = 1.f / (1.f + expf(-ig));
        float fs = 1.f / (1.f + expf(-fg));
        float ct = tanhf(cg);
        float os = 1.f / (1.f + expf(-og));

        size_t idx = ((size_t)b * NN + m) * HH + h;
        float cxv = cx[idx];
        float cyv = mask * (fs * cxv + is * ct) + (1.0f - mask) * cxv;
        float hyv = os * tanhf(cyv);
        hy[idx]  = hyv;
        cyo[idx] = cyv;
    }
}

// ---------------- launch ----------------
extern "C" void kernel_launch(void* const* d_in, const int* in_sizes, int n_in,
                              void* d_out, int out_size) {
    const float* input  = (const float*)d_in[0];
    const float* hx     = (const float*)d_in[1];
    const float* cx     = (const float*)d_in[2];
    const float* G      = (const float*)d_in[3];
    const float* wih    = (const float*)d_in[4];
    const float* whh    = (const float*)d_in[5];
    const float* bhh    = (const float*)d_in[6];
    const int*   ntypes = (const int*)d_in[7];
    const int*   tptr   = (const int*)d_in[8];

    float* hy  = (float*)d_out;
    float* cy  = hy + (size_t)B * NN * HH;
    float* gxo = cy + (size_t)B * NN * HH;

    cudaFuncSetAttribute(gates_gemm, cudaFuncAttributeMaxDynamicSharedMemorySize, SM_BYTES);

    void *p_wih, *p_whh, *p_in, *p_hx;
    cudaGetSymbolAddress(&p_wih, g_wih_h);
    cudaGetSymbolAddress(&p_whh, g_whh_h);
    cudaGetSymbolAddress(&p_in,  g_in_h);
    cudaGetSymbolAddress(&p_hx,  g_hx_h);

    {
        int n8;
        n8 = 5 * FH * II / 8;
        cvt_h_kernel<<<(n8 + 255) / 256, 256>>>((const float4*)wih, (uint4*)p_wih, n8);
        n8 = 5 * FH * HH / 8;
        cvt_h_kernel<<<(n8 + 255) / 256, 256>>>((const float4*)whh, (uint4*)p_whh, n8);
        n8 = B * NN * II / 8;
        cvt_h_kernel<<<(n8 + 255) / 256, 256>>>((const float4*)input, (uint4*)p_in, n8);
        n8 = B * NN * HH / 8;
        cvt_h_kernel<<<(n8 + 255) / 256, 256>>>((const float4*)hx, (uint4*)p_hx, n8);
    }

    gx_kernel<<<1, 512>>>(G, gxo);

    dim3 grid1(FH / TN, B / TM, NN);   // (16, 4, 21)
    gates_gemm<<<grid1, 256, SM_BYTES>>>(bhh, ntypes);

    dim3 grid2(HH / 128, B);           // (8, 512)
    pass2<<<grid2, 128>>>(cx, tptr, hy, cy);
}

// round 7
// speedup vs baseline: 1.0572x; 1.0572x over previous
#include <cuda_runtime.h>
#include <cuda_fp16.h>
#include <cstdint>

// ---------------- problem constants ----------------
#define B   512
#define NN  21
#define II  256
#define HH  1024
#define FH  4096          // 4*HH
#define KK  1280          // II + HH
#define EPS 1e-12f

// ---------------- GEMM tiling ----------------
#define TM 128            // batch rows per CTA
#define TN 256            // out cols per CTA
#define TK 32             // K halves per stage (64 bytes)
#define NSTAGE 4
#define NCHUNK (KK / TK)  // 40
#define PADB 80           // bytes per smem row (64 + 16 pad -> conflict-free ldmatrix)

#define A_STAGE_B (TM * PADB)      // 10240 bytes
#define B_STAGE_B (TN * PADB)      // 20480 bytes
#define STAGE_B   (A_STAGE_B + B_STAGE_B)
#define SM_BYTES  (NSTAGE * STAGE_B)   // 122880

// ---------------- scratch (__device__ globals; no allocation) ----------------
__device__ float  g_gates[(size_t)B * NN * FH];    // [B][NN][4H] pre-mix gates
__device__ float  g_gx[NN * NN];                   // row-L1-normalized G
__device__ __half g_wih_h[(size_t)5 * FH * II];    // fp16 weights
__device__ __half g_whh_h[(size_t)5 * FH * HH];
__device__ __half g_in_h[(size_t)B * NN * II];     // fp16 input
__device__ __half g_hx_h[(size_t)B * NN * HH];     // fp16 hx

// ---------------- helpers ----------------
__device__ __forceinline__ uint32_t smem_u32(const void* p) {
    uint32_t a;
    asm("{ .reg .u64 t; cvta.to.shared.u64 t, %1; cvt.u32.u64 %0, t; }" : "=r"(a) : "l"(p));
    return a;
}
__device__ __forceinline__ void cp16(uint32_t saddr, const void* gptr) {
    asm volatile("cp.async.cg.shared.global [%0], [%1], 16;" :: "r"(saddr), "l"(gptr));
}
__device__ __forceinline__ void ldsm4(uint32_t* r, uint32_t saddr) {
    asm volatile("ldmatrix.sync.aligned.m8n8.x4.shared.b16 {%0,%1,%2,%3}, [%4];"
                 : "=r"(r[0]), "=r"(r[1]), "=r"(r[2]), "=r"(r[3]) : "r"(saddr));
}
__device__ __forceinline__ void mma16(float* c, const uint32_t* a, const uint32_t* b) {
    asm volatile(
        "mma.sync.aligned.m16n8k16.row.col.f32.f16.f16.f32 "
        "{%0,%1,%2,%3}, {%4,%5,%6,%7}, {%8,%9}, {%0,%1,%2,%3};"
        : "+f"(c[0]), "+f"(c[1]), "+f"(c[2]), "+f"(c[3])
        : "r"(a[0]), "r"(a[1]), "r"(a[2]), "r"(a[3]), "r"(b[0]), "r"(b[1]));
}

// ---------------- kernel: fp32 -> fp16 conversion (8 elems/thread) ----------------
__global__ void cvt_h_kernel(const float4* __restrict__ src, uint4* __restrict__ dst, int n8) {
    int i = blockIdx.x * blockDim.x + threadIdx.x;
    if (i < n8) {
        float4 v0 = src[2 * i];
        float4 v1 = src[2 * i + 1];
        __half2 h0 = __floats2half2_rn(v0.x, v0.y);
        __half2 h1 = __floats2half2_rn(v0.z, v0.w);
        __half2 h2 = __floats2half2_rn(v1.x, v1.y);
        __half2 h3 = __floats2half2_rn(v1.z, v1.w);
        uint4 o;
        o.x = *(uint32_t*)&h0; o.y = *(uint32_t*)&h1;
        o.z = *(uint32_t*)&h2; o.w = *(uint32_t*)&h3;
        dst[i] = o;
    }
}

// ---------------- kernel 0: gx normalization ----------------
__global__ void gx_kernel(const float* __restrict__ G, float* __restrict__ gx_out) {
    __shared__ float sG[NN * NN];
    __shared__ float den[NN];
    __shared__ float den2[NN];
    int tid = threadIdx.x;
    for (int i = tid; i < NN * NN; i += blockDim.x) sG[i] = G[i];
    __syncthreads();
    if (tid < NN) {
        float s = 0.f;
        for (int j = 0; j < NN; j++) s += fabsf(sG[tid * NN + j]);
        den[tid] = fmaxf(s, EPS);
    }
    __syncthreads();
    for (int i = tid; i < NN * NN; i += blockDim.x) sG[i] = sG[i] / den[i / NN];
    __syncthreads();
    if (tid < NN) {
        float s = 0.f;
        for (int j = 0; j < NN; j++) s += fabsf(sG[tid * NN + j]);
        den2[tid] = fmaxf(s, EPS);
    }
    __syncthreads();
    for (int i = tid; i < NN * NN; i += blockDim.x) {
        g_gx[i]   = sG[i];
        gx_out[i] = sG[i] / den2[i / NN];
    }
}

// ---------------- kernel 1: fp16 mma.sync gates GEMM, 512 threads ----------------
// g_gates[b][n][o] = [input|hx] @ [Wih|Whh]^T + bias   (fp16 inputs, fp32 accum)
__global__ __launch_bounds__(512, 1)
void gates_gemm(const float* __restrict__ bhh, const int* __restrict__ ntypes) {
    extern __shared__ char smc[];
    const int tid  = threadIdx.x;
    const int lane = tid & 31;
    const int wid  = tid >> 5;

    const int n  = blockIdx.z;
    const int bm = blockIdx.y * TM;
    const int bo = blockIdx.x * TN;
    const int nt = ntypes[n];
    const __half* wih = g_wih_h + (size_t)nt * FH * II;
    const __half* whh = g_whh_h + (size_t)nt * FH * HH;

    const uint32_t sb = smem_u32(smc);

    // warp tiling: 4 (m) x 4 (n), warp tile 32x64
    const int wm = (wid & 3) * 32;
    const int wn = (wid >> 2) * 64;

    // ldmatrix lane byte offsets (validated in round 5)
    const uint32_t aL = (uint32_t)((((lane >> 3) & 1) * 8 + (lane & 7)) * PADB + (lane >> 4) * 16);
    const uint32_t bL = (uint32_t)((((lane >> 4) & 1) * 8 + (lane & 7)) * PADB + ((lane >> 3) & 1) * 16);

    float acc[2][8][4];
#pragma unroll
    for (int i = 0; i < 2; i++)
#pragma unroll
        for (int j = 0; j < 8; j++)
#pragma unroll
            for (int v = 0; v < 4; v++) acc[i][j][v] = 0.f;

    // ---- stage loader: A 512 chunks, B 1024 chunks of 16B; 512 threads ----
    auto load_stage = [&](int kt) {
        const int s  = kt % NSTAGE;
        const int k0 = kt * TK;
        const uint32_t ab = sb + (uint32_t)(s * STAGE_B);
        const uint32_t bb = ab + (uint32_t)A_STAGE_B;
        {
            int r = tid >> 2, c = tid & 3;
            int k = k0 + c * 8;
            const __half* src = (k < II)
                ? g_in_h + ((size_t)(bm + r) * NN + n) * II + k
                : g_hx_h + ((size_t)(bm + r) * NN + n) * HH + (k - II);
            cp16(ab + (uint32_t)(r * PADB + c * 16), src);
        }
#pragma unroll
        for (int i = 0; i < 2; i++) {
            int f = tid + i * 512;
            int r = f >> 2, c = f & 3;
            int k = k0 + c * 8;
            const __half* src = (k < II)
                ? wih + (size_t)(bo + r) * II + k
                : whh + (size_t)(bo + r) * HH + (k - II);
            cp16(bb + (uint32_t)(r * PADB + c * 16), src);
        }
    };

    // prologue
#pragma unroll
    for (int s = 0; s < NSTAGE; s++) {
        load_stage(s);
        asm volatile("cp.async.commit_group;" ::: "memory");
    }

    // mainloop
    for (int kt = 0; kt < NCHUNK; kt++) {
        asm volatile("cp.async.wait_group %0;" :: "n"(NSTAGE - 1) : "memory");
        __syncthreads();

        const int s = kt % NSTAGE;
        const uint32_t sAb = sb + (uint32_t)(s * STAGE_B);
        const uint32_t sBb = sAb + (uint32_t)A_STAGE_B;

#pragma unroll
        for (int ks = 0; ks < TK / 16; ks++) {
            const uint32_t kb = (uint32_t)(ks * 32);
            uint32_t af[2][4];
#pragma unroll
            for (int mi = 0; mi < 2; mi++)
                ldsm4(af[mi], sAb + (uint32_t)((wm + mi * 16) * PADB) + kb + aL);
            uint32_t bq[4][4];
#pragma unroll
            for (int np = 0; np < 4; np++)
                ldsm4(bq[np], sBb + (uint32_t)((wn + np * 16) * PADB) + kb + bL);
#pragma unroll
            for (int mi = 0; mi < 2; mi++)
#pragma unroll
                for (int ni = 0; ni < 8; ni++)
                    mma16(acc[mi][ni], af[mi], &bq[ni >> 1][(ni & 1) * 2]);
        }
        __syncthreads();
        if (kt + NSTAGE < NCHUNK) load_stage(kt + NSTAGE);
        asm volatile("cp.async.commit_group;" ::: "memory");
    }

    // ---- epilogue: bias + store ----
    const int lr = lane >> 2;
    const int lq = lane & 3;
    const float* brow = bhh + (size_t)nt * FH + bo;
#pragma unroll
    for (int mi = 0; mi < 2; mi++) {
        int r0 = wm + mi * 16 + lr;
        float* out0 = g_gates + ((size_t)(bm + r0)     * NN + n) * FH + bo;
        float* out1 = g_gates + ((size_t)(bm + r0 + 8) * NN + n) * FH + bo;
#pragma unroll
        for (int ni = 0; ni < 8; ni++) {
            int col = wn + ni * 8 + lq * 2;
            float2 bv = *(const float2*)(brow + col);
            float2 v0 = make_float2(acc[mi][ni][0] + bv.x, acc[mi][ni][1] + bv.y);
            float2 v1 = make_float2(acc[mi][ni][2] + bv.x, acc[mi][ni][3] + bv.y);
            *(float2*)(out0 + col) = v0;
            *(float2*)(out1 + col) = v1;
        }
    }
}

// ---------------- kernel 2: graph mix over n + LSTM epilogue ----------------
__global__ __launch_bounds__(128)
void pass2(const float* __restrict__ cx, const int* __restrict__ tptr,
           float* __restrict__ hy, float* __restrict__ cyo) {
    __shared__ float sgx[NN * NN];
    const int tid = threadIdx.x;
    for (int i = tid; i < NN * NN; i += 128) sgx[i] = g_gx[i];
    __syncthreads();

    const int b = blockIdx.y;
    const int h = blockIdx.x * 128 + tid;

    const float t1    = (float)(*tptr) + 1.0f;
    const float phase = floorf((float)h / (float)(HH - 1) * 8.0f + 1.0f);
    const float mask  = (fmodf(t1, phase) < 0.01f) ? 1.0f : 0.0f;

    float rg0[NN], rg1[NN], rg2[NN], rg3[NN];
    const float* gbase = g_gates + (size_t)b * NN * FH + h;
#pragma unroll
    for (int nI = 0; nI < NN; nI++) {
        rg0[nI] = gbase[(size_t)nI * FH];
        rg1[nI] = gbase[(size_t)nI * FH + HH];
        rg2[nI] = gbase[(size_t)nI * FH + 2 * HH];
        rg3[nI] = gbase[(size_t)nI * FH + 3 * HH];
    }

#pragma unroll 1
    for (int m = 0; m < NN; m++) {
        float ig = 0.f, fg = 0.f, cg = 0.f, og = 0.f;
#pragma unroll
        for (int nI = 0; nI < NN; nI++) {
            float w = sgx[m * NN + nI];
            ig = fmaf(w, rg0[nI], ig);
            fg = fmaf(w, rg1[nI], fg);
            cg = fmaf(w, rg2[nI], cg);
            og = fmaf(w, rg3[nI], og);
        }
        float is = 1.f / (1.f + expf(-ig));
        float fs = 1.f / (1.f + expf(-fg));
        float ct = tanhf(cg);
        float os = 1.f / (1.f + expf(-og));

        size_t idx = ((size_t)b * NN + m) * HH + h;
        float cxv = cx[idx];
        float cyv = mask * (fs * cxv + is * ct) + (1.0f - mask) * cxv;
        float hyv = os * tanhf(cyv);
        hy[idx]  = hyv;
        cyo[idx] = cyv;
    }
}

// ---------------- launch ----------------
extern "C" void kernel_launch(void* const* d_in, const int* in_sizes, int n_in,
                              void* d_out, int out_size) {
    const float* input  = (const float*)d_in[0];
    const float* hx     = (const float*)d_in[1];
    const float* cx     = (const float*)d_in[2];
    const float* G      = (const float*)d_in[3];
    const float* wih    = (const float*)d_in[4];
    const float* whh    = (const float*)d_in[5];
    const float* bhh    = (const float*)d_in[6];
    const int*   ntypes = (const int*)d_in[7];
    const int*   tptr   = (const int*)d_in[8];

    float* hy  = (float*)d_out;
    float* cy  = hy + (size_t)B * NN * HH;
    float* gxo = cy + (size_t)B * NN * HH;

    cudaFuncSetAttribute(gates_gemm, cudaFuncAttributeMaxDynamicSharedMemorySize, SM_BYTES);

    void *p_wih, *p_whh, *p_in, *p_hx;
    cudaGetSymbolAddress(&p_wih, g_wih_h);
    cudaGetSymbolAddress(&p_whh, g_whh_h);
    cudaGetSymbolAddress(&p_in,  g_in_h);
    cudaGetSymbolAddress(&p_hx,  g_hx_h);

    {
        int n8;
        n8 = 5 * FH * II / 8;
        cvt_h_kernel<<<(n8 + 255) / 256, 256>>>((const float4*)wih, (uint4*)p_wih, n8);
        n8 = 5 * FH * HH / 8;
        cvt_h_kernel<<<(n8 + 255) / 256, 256>>>((const float4*)whh, (uint4*)p_whh, n8);
        n8 = B * NN * II / 8;
        cvt_h_kernel<<<(n8 + 255) / 256, 256>>>((const float4*)input, (uint4*)p_in, n8);
        n8 = B * NN * HH / 8;
        cvt_h_kernel<<<(n8 + 255) / 256, 256>>>((const float4*)hx, (uint4*)p_hx, n8);
    }

    gx_kernel<<<1, 512>>>(G, gxo);

    dim3 grid1(FH / TN, B / TM, NN);   // (16, 4, 21)
    gates_gemm<<<grid1, 512, SM_BYTES>>>(bhh, ntypes);

    dim3 grid2(HH / 128, B);           // (8, 512)
    pass2<<<grid2, 128>>>(cx, tptr, hy, cy);
}

// round 8
// speedup vs baseline: 1.0811x; 1.0226x over previous
#include <cuda_runtime.h>
#include <cuda_fp16.h>
#include <cstdint>

// ---------------- problem constants ----------------
#define B   512
#define NN  21
#define II  256
#define HH  1024
#define FH  4096          // 4*HH
#define KK  1280          // II + HH
#define EPS 1e-12f

// ---------------- GEMM tiling ----------------
#define TM 128            // batch rows per CTA
#define TN 256            // out cols per CTA
#define TK 32             // K halves per stage (64 bytes)
#define NSTAGE 4
#define NCHUNK (KK / TK)  // 40
#define PADB 80           // bytes per smem row (64 + 16 pad -> conflict-free ldmatrix)

#define A_STAGE_B (TM * PADB)      // 10240 bytes
#define B_STAGE_B (TN * PADB)      // 20480 bytes
#define STAGE_B   (A_STAGE_B + B_STAGE_B)
#define SM_BYTES  (NSTAGE * STAGE_B)   // 122880

// cvt region sizes in 8-element units
#define N8_WIH (5 * FH * II / 8)   // 655360
#define N8_WHH (5 * FH * HH / 8)   // 2621440
#define N8_IN  (B * NN * II / 8)   // 344064
#define N8_HX  (B * NN * HH / 8)   // 1376256
#define N8_TOT (N8_WIH + N8_WHH + N8_IN + N8_HX)

// ---------------- scratch (__device__ globals; no allocation) ----------------
__device__ __half g_gates_h[(size_t)B * NN * FH];  // [B][NN][4H] pre-mix gates (fp16)
__device__ float  g_gx[NN * NN];                   // row-L1-normalized G
__device__ __half g_wih_h[(size_t)5 * FH * II];    // fp16 weights
__device__ __half g_whh_h[(size_t)5 * FH * HH];
__device__ __half g_in_h[(size_t)B * NN * II];     // fp16 input
__device__ __half g_hx_h[(size_t)B * NN * HH];     // fp16 hx

// ---------------- helpers ----------------
__device__ __forceinline__ uint32_t smem_u32(const void* p) {
    uint32_t a;
    asm("{ .reg .u64 t; cvta.to.shared.u64 t, %1; cvt.u32.u64 %0, t; }" : "=r"(a) : "l"(p));
    return a;
}
__device__ __forceinline__ void cp16(uint32_t saddr, const void* gptr) {
    asm volatile("cp.async.cg.shared.global [%0], [%1], 16;" :: "r"(saddr), "l"(gptr));
}
__device__ __forceinline__ void ldsm4(uint32_t* r, uint32_t saddr) {
    asm volatile("ldmatrix.sync.aligned.m8n8.x4.shared.b16 {%0,%1,%2,%3}, [%4];"
                 : "=r"(r[0]), "=r"(r[1]), "=r"(r[2]), "=r"(r[3]) : "r"(saddr));
}
__device__ __forceinline__ void mma16(float* c, const uint32_t* a, const uint32_t* b) {
    asm volatile(
        "mma.sync.aligned.m16n8k16.row.col.f32.f16.f16.f32 "
        "{%0,%1,%2,%3}, {%4,%5,%6,%7}, {%8,%9}, {%0,%1,%2,%3};"
        : "+f"(c[0]), "+f"(c[1]), "+f"(c[2]), "+f"(c[3])
        : "r"(a[0]), "r"(a[1]), "r"(a[2]), "r"(a[3]), "r"(b[0]), "r"(b[1]));
}

// ---------------- kernel: fused fp32 -> fp16 conversion for all 4 tensors ----------------
__global__ void cvt_all_kernel(const float4* __restrict__ wih, const float4* __restrict__ whh,
                               const float4* __restrict__ in,  const float4* __restrict__ hx,
                               uint4* __restrict__ o_wih, uint4* __restrict__ o_whh,
                               uint4* __restrict__ o_in,  uint4* __restrict__ o_hx) {
    int i = blockIdx.x * blockDim.x + threadIdx.x;
    if (i >= N8_TOT) return;
    const float4* s;
    uint4* d;
    int j = i;
    if (j < N8_WIH) { s = wih; d = o_wih; }
    else {
        j -= N8_WIH;
        if (j < N8_WHH) { s = whh; d = o_whh; }
        else {
            j -= N8_WHH;
            if (j < N8_IN) { s = in; d = o_in; }
            else { j -= N8_IN; s = hx; d = o_hx; }
        }
    }
    float4 v0 = s[2 * j];
    float4 v1 = s[2 * j + 1];
    __half2 h0 = __floats2half2_rn(v0.x, v0.y);
    __half2 h1 = __floats2half2_rn(v0.z, v0.w);
    __half2 h2 = __floats2half2_rn(v1.x, v1.y);
    __half2 h3 = __floats2half2_rn(v1.z, v1.w);
    uint4 o;
    o.x = *(uint32_t*)&h0; o.y = *(uint32_t*)&h1;
    o.z = *(uint32_t*)&h2; o.w = *(uint32_t*)&h3;
    d[j] = o;
}

// ---------------- kernel 0: gx normalization ----------------
__global__ void gx_kernel(const float* __restrict__ G, float* __restrict__ gx_out) {
    __shared__ float sG[NN * NN];
    __shared__ float den[NN];
    __shared__ float den2[NN];
    int tid = threadIdx.x;
    for (int i = tid; i < NN * NN; i += blockDim.x) sG[i] = G[i];
    __syncthreads();
    if (tid < NN) {
        float s = 0.f;
        for (int j = 0; j < NN; j++) s += fabsf(sG[tid * NN + j]);
        den[tid] = fmaxf(s, EPS);
    }
    __syncthreads();
    for (int i = tid; i < NN * NN; i += blockDim.x) sG[i] = sG[i] / den[i / NN];
    __syncthreads();
    if (tid < NN) {
        float s = 0.f;
        for (int j = 0; j < NN; j++) s += fabsf(sG[tid * NN + j]);
        den2[tid] = fmaxf(s, EPS);
    }
    __syncthreads();
    for (int i = tid; i < NN * NN; i += blockDim.x) {
        g_gx[i]   = sG[i];
        gx_out[i] = sG[i] / den2[i / NN];
    }
}

// ---------------- kernel 1: fp16 mma.sync gates GEMM, 512 threads ----------------
__global__ __launch_bounds__(512, 1)
void gates_gemm(const float* __restrict__ bhh, const int* __restrict__ ntypes) {
    extern __shared__ char smc[];
    const int tid  = threadIdx.x;
    const int lane = tid & 31;
    const int wid  = tid >> 5;

    const int n  = blockIdx.z;
    const int bm = blockIdx.y * TM;
    const int bo = blockIdx.x * TN;
    const int nt = ntypes[n];
    const __half* wih = g_wih_h + (size_t)nt * FH * II;
    const __half* whh = g_whh_h + (size_t)nt * FH * HH;

    const uint32_t sb = smem_u32(smc);

    // warp tiling: 4 (m) x 4 (n), warp tile 32x64
    const int wm = (wid & 3) * 32;
    const int wn = (wid >> 2) * 64;

    const uint32_t aL = (uint32_t)((((lane >> 3) & 1) * 8 + (lane & 7)) * PADB + (lane >> 4) * 16);
    const uint32_t bL = (uint32_t)((((lane >> 4) & 1) * 8 + (lane & 7)) * PADB + ((lane >> 3) & 1) * 16);

    float acc[2][8][4];
#pragma unroll
    for (int i = 0; i < 2; i++)
#pragma unroll
        for (int j = 0; j < 8; j++)
#pragma unroll
            for (int v = 0; v < 4; v++) acc[i][j][v] = 0.f;

    auto load_stage = [&](int kt) {
        const int s  = kt % NSTAGE;
        const int k0 = kt * TK;
        const uint32_t ab = sb + (uint32_t)(s * STAGE_B);
        const uint32_t bb = ab + (uint32_t)A_STAGE_B;
        {
            int r = tid >> 2, c = tid & 3;
            int k = k0 + c * 8;
            const __half* src = (k < II)
                ? g_in_h + ((size_t)(bm + r) * NN + n) * II + k
                : g_hx_h + ((size_t)(bm + r) * NN + n) * HH + (k - II);
            cp16(ab + (uint32_t)(r * PADB + c * 16), src);
        }
#pragma unroll
        for (int i = 0; i < 2; i++) {
            int f = tid + i * 512;
            int r = f >> 2, c = f & 3;
            int k = k0 + c * 8;
            const __half* src = (k < II)
                ? wih + (size_t)(bo + r) * II + k
                : whh + (size_t)(bo + r) * HH + (k - II);
            cp16(bb + (uint32_t)(r * PADB + c * 16), src);
        }
    };

#pragma unroll
    for (int s = 0; s < NSTAGE; s++) {
        load_stage(s);
        asm volatile("cp.async.commit_group;" ::: "memory");
    }

    for (int kt = 0; kt < NCHUNK; kt++) {
        asm volatile("cp.async.wait_group %0;" :: "n"(NSTAGE - 1) : "memory");
        __syncthreads();

        const int s = kt % NSTAGE;
        const uint32_t sAb = sb + (uint32_t)(s * STAGE_B);
        const uint32_t sBb = sAb + (uint32_t)A_STAGE_B;

#pragma unroll
        for (int ks = 0; ks < TK / 16; ks++) {
            const uint32_t kb = (uint32_t)(ks * 32);
            uint32_t af[2][4];
#pragma unroll
            for (int mi = 0; mi < 2; mi++)
                ldsm4(af[mi], sAb + (uint32_t)((wm + mi * 16) * PADB) + kb + aL);
            uint32_t bq[4][4];
#pragma unroll
            for (int np = 0; np < 4; np++)
                ldsm4(bq[np], sBb + (uint32_t)((wn + np * 16) * PADB) + kb + bL);
#pragma unroll
            for (int mi = 0; mi < 2; mi++)
#pragma unroll
                for (int ni = 0; ni < 8; ni++)
                    mma16(acc[mi][ni], af[mi], &bq[ni >> 1][(ni & 1) * 2]);
        }
        __syncthreads();
        if (kt + NSTAGE < NCHUNK) load_stage(kt + NSTAGE);
        asm volatile("cp.async.commit_group;" ::: "memory");
    }

    // ---- epilogue: bias + fp16 store ----
    const int lr = lane >> 2;
    const int lq = lane & 3;
    const float* brow = bhh + (size_t)nt * FH + bo;
#pragma unroll
    for (int mi = 0; mi < 2; mi++) {
        int r0 = wm + mi * 16 + lr;
        __half* out0 = g_gates_h + ((size_t)(bm + r0)     * NN + n) * FH + bo;
        __half* out1 = g_gates_h + ((size_t)(bm + r0 + 8) * NN + n) * FH + bo;
#pragma unroll
        for (int ni = 0; ni < 8; ni++) {
            int col = wn + ni * 8 + lq * 2;
            float2 bv = *(const float2*)(brow + col);
            __half2 v0 = __floats2half2_rn(acc[mi][ni][0] + bv.x, acc[mi][ni][1] + bv.y);
            __half2 v1 = __floats2half2_rn(acc[mi][ni][2] + bv.x, acc[mi][ni][3] + bv.y);
            *(__half2*)(out0 + col) = v0;
            *(__half2*)(out1 + col) = v1;
        }
    }
}

// ---------------- kernel 2: graph mix over n + LSTM epilogue ----------------
__global__ __launch_bounds__(128)
void pass2(const float* __restrict__ cx, const int* __restrict__ tptr,
           float* __restrict__ hy, float* __restrict__ cyo) {
    __shared__ float sgx[NN * NN];
    const int tid = threadIdx.x;
    for (int i = tid; i < NN * NN; i += 128) sgx[i] = g_gx[i];
    __syncthreads();

    const int b = blockIdx.y;
    const int h = blockIdx.x * 128 + tid;

    const float t1    = (float)(*tptr) + 1.0f;
    const float phase = floorf((float)h / (float)(HH - 1) * 8.0f + 1.0f);
    const float mask  = (fmodf(t1, phase) < 0.01f) ? 1.0f : 0.0f;

    float rg0[NN], rg1[NN], rg2[NN], rg3[NN];
    const __half* gbase = g_gates_h + (size_t)b * NN * FH + h;
#pragma unroll
    for (int nI = 0; nI < NN; nI++) {
        rg0[nI] = __half2float(gbase[(size_t)nI * FH]);
        rg1[nI] = __half2float(gbase[(size_t)nI * FH + HH]);
        rg2[nI] = __half2float(gbase[(size_t)nI * FH + 2 * HH]);
        rg3[nI] = __half2float(gbase[(size_t)nI * FH + 3 * HH]);
    }

#pragma unroll 1
    for (int m = 0; m < NN; m++) {
        float ig = 0.f, fg = 0.f, cg = 0.f, og = 0.f;
#pragma unroll
        for (int nI = 0; nI < NN; nI++) {
            float w = sgx[m * NN + nI];
            ig = fmaf(w, rg0[nI], ig);
            fg = fmaf(w, rg1[nI], fg);
            cg = fmaf(w, rg2[nI], cg);
            og = fmaf(w, rg3[nI], og);
        }
        float is = 1.f / (1.f + __expf(-ig));
        float fs = 1.f / (1.f + __expf(-fg));
        float ct = tanhf(cg);
        float os = 1.f / (1.f + __expf(-og));

        size_t idx = ((size_t)b * NN + m) * HH + h;
        float cxv = cx[idx];
        float cyv = mask * (fs * cxv + is * ct) + (1.0f - mask) * cxv;
        float hyv = os * tanhf(cyv);
        hy[idx]  = hyv;
        cyo[idx] = cyv;
    }
}

// ---------------- launch ----------------
extern "C" void kernel_launch(void* const* d_in, const int* in_sizes, int n_in,
                              void* d_out, int out_size) {
    const float* input  = (const float*)d_in[0];
    const float* hx     = (const float*)d_in[1];
    const float* cx     = (const float*)d_in[2];
    const float* G      = (const float*)d_in[3];
    const float* wih    = (const float*)d_in[4];
    const float* whh    = (const float*)d_in[5];
    const float* bhh    = (const float*)d_in[6];
    const int*   ntypes = (const int*)d_in[7];
    const int*   tptr   = (const int*)d_in[8];

    float* hy  = (float*)d_out;
    float* cy  = hy + (size_t)B * NN * HH;
    float* gxo = cy + (size_t)B * NN * HH;

    cudaFuncSetAttribute(gates_gemm, cudaFuncAttributeMaxDynamicSharedMemorySize, SM_BYTES);

    void *p_wih, *p_whh, *p_in, *p_hx;
    cudaGetSymbolAddress(&p_wih, g_wih_h);
    cudaGetSymbolAddress(&p_whh, g_whh_h);
    cudaGetSymbolAddress(&p_in,  g_in_h);
    cudaGetSymbolAddress(&p_hx,  g_hx_h);

    cvt_all_kernel<<<(N8_TOT + 255) / 256, 256>>>(
        (const float4*)wih, (const float4*)whh, (const float4*)input, (const float4*)hx,
        (uint4*)p_wih, (uint4*)p_whh, (uint4*)p_in, (uint4*)p_hx);

    gx_kernel<<<1, 512>>>(G, gxo);

    dim3 grid1(FH / TN, B / TM, NN);   // (16, 4, 21)
    gates_gemm<<<grid1, 512, SM_BYTES>>>(bhh, ntypes);

    dim3 grid2(HH / 128, B);           // (8, 512)
    pass2<<<grid2, 128>>>(cx, tptr, hy, cy);
}

// round 9
// speedup vs baseline: 1.2473x; 1.1538x over previous
#include <cuda_runtime.h>
#include <cuda_fp16.h>
#include <cstdint>

// ---------------- problem constants ----------------
#define B   512
#define NN  21
#define II  256
#define HH  1024
#define FH  4096          // 4*HH
#define KK  1280          // II + HH
#define EPS 1e-12f

// ---------------- GEMM tiling ----------------
#define TM 128
#define TN 256
#define TK 32
#define NSTAGE 4
#define NCHUNK (KK / TK)
#define PADB 80

#define A_STAGE_B (TM * PADB)
#define B_STAGE_B (TN * PADB)
#define STAGE_B   (A_STAGE_B + B_STAGE_B)
#define SM_BYTES  (NSTAGE * STAGE_B)

// cvt region sizes in 8-element units
#define N8_WIH (5 * FH * II / 8)
#define N8_WHH (5 * FH * HH / 8)
#define N8_IN  (B * NN * II / 8)
#define N8_HX  (B * NN * HH / 8)
#define N8_TOT (N8_WIH + N8_WHH + N8_IN + N8_HX)

// ---------------- scratch ----------------
__device__ __half  g_gates_h[(size_t)B * NN * FH];
__device__ __half2 g_gx2[NN * NN];                 // (w,w) pairs of normalized gx
__device__ __half  g_wih_h[(size_t)5 * FH * II];
__device__ __half  g_whh_h[(size_t)5 * FH * HH];
__device__ __half  g_in_h[(size_t)B * NN * II];
__device__ __half  g_hx_h[(size_t)B * NN * HH];

// ---------------- helpers ----------------
__device__ __forceinline__ uint32_t smem_u32(const void* p) {
    uint32_t a;
    asm("{ .reg .u64 t; cvta.to.shared.u64 t, %1; cvt.u32.u64 %0, t; }" : "=r"(a) : "l"(p));
    return a;
}
__device__ __forceinline__ void cp16(uint32_t saddr, const void* gptr) {
    asm volatile("cp.async.cg.shared.global [%0], [%1], 16;" :: "r"(saddr), "l"(gptr));
}
__device__ __forceinline__ void ldsm4(uint32_t* r, uint32_t saddr) {
    asm volatile("ldmatrix.sync.aligned.m8n8.x4.shared.b16 {%0,%1,%2,%3}, [%4];"
                 : "=r"(r[0]), "=r"(r[1]), "=r"(r[2]), "=r"(r[3]) : "r"(saddr));
}
__device__ __forceinline__ void mma16(float* c, const uint32_t* a, const uint32_t* b) {
    asm volatile(
        "mma.sync.aligned.m16n8k16.row.col.f32.f16.f16.f32 "
        "{%0,%1,%2,%3}, {%4,%5,%6,%7}, {%8,%9}, {%0,%1,%2,%3};"
        : "+f"(c[0]), "+f"(c[1]), "+f"(c[2]), "+f"(c[3])
        : "r"(a[0]), "r"(a[1]), "r"(a[2]), "r"(a[3]), "r"(b[0]), "r"(b[1]));
}
__device__ __forceinline__ float fsig(float x) {
    return __fdividef(1.f, 1.f + __expf(-x));
}
__device__ __forceinline__ float ftanh(float x) {
    return __fdividef(2.f, 1.f + __expf(-2.f * x)) - 1.f;
}

// ---------------- kernel: fused fp32 -> fp16 conversion ----------------
__global__ void cvt_all_kernel(const float4* __restrict__ wih, const float4* __restrict__ whh,
                               const float4* __restrict__ in,  const float4* __restrict__ hx,
                               uint4* __restrict__ o_wih, uint4* __restrict__ o_whh,
                               uint4* __restrict__ o_in,  uint4* __restrict__ o_hx) {
    int i = blockIdx.x * blockDim.x + threadIdx.x;
    if (i >= N8_TOT) return;
    const float4* s;
    uint4* d;
    int j = i;
    if (j < N8_WIH) { s = wih; d = o_wih; }
    else {
        j -= N8_WIH;
        if (j < N8_WHH) { s = whh; d = o_whh; }
        else {
            j -= N8_WHH;
            if (j < N8_IN) { s = in; d = o_in; }
            else { j -= N8_IN; s = hx; d = o_hx; }
        }
    }
    float4 v0 = s[2 * j];
    float4 v1 = s[2 * j + 1];
    __half2 h0 = __floats2half2_rn(v0.x, v0.y);
    __half2 h1 = __floats2half2_rn(v0.z, v0.w);
    __half2 h2 = __floats2half2_rn(v1.x, v1.y);
    __half2 h3 = __floats2half2_rn(v1.z, v1.w);
    uint4 o;
    o.x = *(uint32_t*)&h0; o.y = *(uint32_t*)&h1;
    o.z = *(uint32_t*)&h2; o.w = *(uint32_t*)&h3;
    d[j] = o;
}

// ---------------- kernel 0: gx normalization ----------------
__global__ void gx_kernel(const float* __restrict__ G, float* __restrict__ gx_out) {
    __shared__ float sG[NN * NN];
    __shared__ float den[NN];
    __shared__ float den2[NN];
    int tid = threadIdx.x;
    for (int i = tid; i < NN * NN; i += blockDim.x) sG[i] = G[i];
    __syncthreads();
    if (tid < NN) {
        float s = 0.f;
        for (int j = 0; j < NN; j++) s += fabsf(sG[tid * NN + j]);
        den[tid] = fmaxf(s, EPS);
    }
    __syncthreads();
    for (int i = tid; i < NN * NN; i += blockDim.x) sG[i] = sG[i] / den[i / NN];
    __syncthreads();
    if (tid < NN) {
        float s = 0.f;
        for (int j = 0; j < NN; j++) s += fabsf(sG[tid * NN + j]);
        den2[tid] = fmaxf(s, EPS);
    }
    __syncthreads();
    for (int i = tid; i < NN * NN; i += blockDim.x) {
        float w = sG[i];
        g_gx2[i]  = __float2half2_rn(w);
        gx_out[i] = w / den2[i / NN];
    }
}

// ---------------- kernel 1: fp16 mma.sync gates GEMM, 512 threads ----------------
__global__ __launch_bounds__(512, 1)
void gates_gemm(const float* __restrict__ bhh, const int* __restrict__ ntypes) {
    extern __shared__ char smc[];
    const int tid  = threadIdx.x;
    const int lane = tid & 31;
    const int wid  = tid >> 5;

    const int n  = blockIdx.z;
    const int bm = blockIdx.y * TM;
    const int bo = blockIdx.x * TN;
    const int nt = ntypes[n];
    const __half* wih = g_wih_h + (size_t)nt * FH * II;
    const __half* whh = g_whh_h + (size_t)nt * FH * HH;

    const uint32_t sb = smem_u32(smc);

    const int wm = (wid & 3) * 32;
    const int wn = (wid >> 2) * 64;

    const uint32_t aL = (uint32_t)((((lane >> 3) & 1) * 8 + (lane & 7)) * PADB + (lane >> 4) * 16);
    const uint32_t bL = (uint32_t)((((lane >> 4) & 1) * 8 + (lane & 7)) * PADB + ((lane >> 3) & 1) * 16);

    float acc[2][8][4];
#pragma unroll
    for (int i = 0; i < 2; i++)
#pragma unroll
        for (int j = 0; j < 8; j++)
#pragma unroll
            for (int v = 0; v < 4; v++) acc[i][j][v] = 0.f;

    auto load_stage = [&](int kt) {
        const int s  = kt % NSTAGE;
        const int k0 = kt * TK;
        const uint32_t ab = sb + (uint32_t)(s * STAGE_B);
        const uint32_t bb = ab + (uint32_t)A_STAGE_B;
        {
            int r = tid >> 2, c = tid & 3;
            int k = k0 + c * 8;
            const __half* src = (k < II)
                ? g_in_h + ((size_t)(bm + r) * NN + n) * II + k
                : g_hx_h + ((size_t)(bm + r) * NN + n) * HH + (k - II);
            cp16(ab + (uint32_t)(r * PADB + c * 16), src);
        }
#pragma unroll
        for (int i = 0; i < 2; i++) {
            int f = tid + i * 512;
            int r = f >> 2, c = f & 3;
            int k = k0 + c * 8;
            const __half* src = (k < II)
                ? wih + (size_t)(bo + r) * II + k
                : whh + (size_t)(bo + r) * HH + (k - II);
            cp16(bb + (uint32_t)(r * PADB + c * 16), src);
        }
    };

#pragma unroll
    for (int s = 0; s < NSTAGE; s++) {
        load_stage(s);
        asm volatile("cp.async.commit_group;" ::: "memory");
    }

    for (int kt = 0; kt < NCHUNK; kt++) {
        asm volatile("cp.async.wait_group %0;" :: "n"(NSTAGE - 1) : "memory");
        __syncthreads();

        const int s = kt % NSTAGE;
        const uint32_t sAb = sb + (uint32_t)(s * STAGE_B);
        const uint32_t sBb = sAb + (uint32_t)A_STAGE_B;

#pragma unroll
        for (int ks = 0; ks < TK / 16; ks++) {
            const uint32_t kb = (uint32_t)(ks * 32);
            uint32_t af[2][4];
#pragma unroll
            for (int mi = 0; mi < 2; mi++)
                ldsm4(af[mi], sAb + (uint32_t)((wm + mi * 16) * PADB) + kb + aL);
            uint32_t bq[4][4];
#pragma unroll
            for (int np = 0; np < 4; np++)
                ldsm4(bq[np], sBb + (uint32_t)((wn + np * 16) * PADB) + kb + bL);
#pragma unroll
            for (int mi = 0; mi < 2; mi++)
#pragma unroll
                for (int ni = 0; ni < 8; ni++)
                    mma16(acc[mi][ni], af[mi], &bq[ni >> 1][(ni & 1) * 2]);
        }
        __syncthreads();
        if (kt + NSTAGE < NCHUNK) load_stage(kt + NSTAGE);
        asm volatile("cp.async.commit_group;" ::: "memory");
    }

    const int lr = lane >> 2;
    const int lq = lane & 3;
    const float* brow = bhh + (size_t)nt * FH + bo;
#pragma unroll
    for (int mi = 0; mi < 2; mi++) {
        int r0 = wm + mi * 16 + lr;
        __half* out0 = g_gates_h + ((size_t)(bm + r0)     * NN + n) * FH + bo;
        __half* out1 = g_gates_h + ((size_t)(bm + r0 + 8) * NN + n) * FH + bo;
#pragma unroll
        for (int ni = 0; ni < 8; ni++) {
            int col = wn + ni * 8 + lq * 2;
            float2 bv = *(const float2*)(brow + col);
            __half2 v0 = __floats2half2_rn(acc[mi][ni][0] + bv.x, acc[mi][ni][1] + bv.y);
            __half2 v1 = __floats2half2_rn(acc[mi][ni][2] + bv.x, acc[mi][ni][3] + bv.y);
            *(__half2*)(out0 + col) = v0;
            *(__half2*)(out1 + col) = v1;
        }
    }
}

// ---------------- kernel 2: graph mix + LSTM, 2 h per thread via half2 ----------------
__global__ __launch_bounds__(128)
void pass2(const float* __restrict__ cx, const int* __restrict__ tptr,
           float* __restrict__ hy, float* __restrict__ cyo) {
    __shared__ __half2 sgx[NN * NN];
    const int tid = threadIdx.x;
    for (int i = tid; i < NN * NN; i += 128) sgx[i] = g_gx2[i];
    __syncthreads();

    const int b = blockIdx.y;
    const int h = blockIdx.x * 256 + tid * 2;   // this thread: h, h+1

    const float t1 = (float)(*tptr) + 1.0f;
    const float ph0 = floorf((float)h       / (float)(HH - 1) * 8.0f + 1.0f);
    const float ph1 = floorf((float)(h + 1) / (float)(HH - 1) * 8.0f + 1.0f);
    const float mk0 = (fmodf(t1, ph0) < 0.01f) ? 1.0f : 0.0f;
    const float mk1 = (fmodf(t1, ph1) < 0.01f) ? 1.0f : 0.0f;

    // gate fragments for all 21 nodes, 4 gates, 2 h lanes
    __half2 rg0[NN], rg1[NN], rg2[NN], rg3[NN];
    const __half* gbase = g_gates_h + (size_t)b * NN * FH + h;
#pragma unroll
    for (int nI = 0; nI < NN; nI++) {
        const __half* p = gbase + (size_t)nI * FH;
        rg0[nI] = *(const __half2*)(p);
        rg1[nI] = *(const __half2*)(p + HH);
        rg2[nI] = *(const __half2*)(p + 2 * HH);
        rg3[nI] = *(const __half2*)(p + 3 * HH);
    }

#pragma unroll 1
    for (int m = 0; m < NN; m++) {
        const __half2* wrow = &sgx[m * NN];
        __half2 z = __float2half2_rn(0.f);
        __half2 i0 = z, i1 = z, f0 = z, f1 = z, c0 = z, c1 = z, o0 = z, o1 = z;
#pragma unroll
        for (int nI = 0; nI < NN; nI++) {
            __half2 w = wrow[nI];
            if (nI & 1) {
                i1 = __hfma2(w, rg0[nI], i1);
                f1 = __hfma2(w, rg1[nI], f1);
                c1 = __hfma2(w, rg2[nI], c1);
                o1 = __hfma2(w, rg3[nI], o1);
            } else {
                i0 = __hfma2(w, rg0[nI], i0);
                f0 = __hfma2(w, rg1[nI], f0);
                c0 = __hfma2(w, rg2[nI], c0);
                o0 = __hfma2(w, rg3[nI], o0);
            }
        }
        float2 ig = __half22float2(__hadd2(i0, i1));
        float2 fg = __half22float2(__hadd2(f0, f1));
        float2 cg = __half22float2(__hadd2(c0, c1));
        float2 og = __half22float2(__hadd2(o0, o1));

        size_t idx = ((size_t)b * NN + m) * HH + h;
        float2 cxv = *(const float2*)(cx + idx);

        float isx = fsig(ig.x), isy = fsig(ig.y);
        float fsx = fsig(fg.x), fsy = fsig(fg.y);
        float ctx = ftanh(cg.x), cty = ftanh(cg.y);
        float osx = fsig(og.x), osy = fsig(og.y);

        float cyx = mk0 * (fsx * cxv.x + isx * ctx) + (1.0f - mk0) * cxv.x;
        float cyy = mk1 * (fsy * cxv.y + isy * cty) + (1.0f - mk1) * cxv.y;
        float hyx = osx * ftanh(cyx);
        float hyy = osy * ftanh(cyy);

        *(float2*)(hy + idx)  = make_float2(hyx, hyy);
        *(float2*)(cyo + idx) = make_float2(cyx, cyy);
    }
}

// ---------------- launch ----------------
extern "C" void kernel_launch(void* const* d_in, const int* in_sizes, int n_in,
                              void* d_out, int out_size) {
    const float* input  = (const float*)d_in[0];
    const float* hx     = (const float*)d_in[1];
    const float* cx     = (const float*)d_in[2];
    const float* G      = (const float*)d_in[3];
    const float* wih    = (const float*)d_in[4];
    const float* whh    = (const float*)d_in[5];
    const float* bhh    = (const float*)d_in[6];
    const int*   ntypes = (const int*)d_in[7];
    const int*   tptr   = (const int*)d_in[8];

    float* hy  = (float*)d_out;
    float* cy  = hy + (size_t)B * NN * HH;
    float* gxo = cy + (size_t)B * NN * HH;

    cudaFuncSetAttribute(gates_gemm, cudaFuncAttributeMaxDynamicSharedMemorySize, SM_BYTES);

    void *p_wih, *p_whh, *p_in, *p_hx;
    cudaGetSymbolAddress(&p_wih, g_wih_h);
    cudaGetSymbolAddress(&p_whh, g_whh_h);
    cudaGetSymbolAddress(&p_in,  g_in_h);
    cudaGetSymbolAddress(&p_hx,  g_hx_h);

    cvt_all_kernel<<<(N8_TOT + 255) / 256, 256>>>(
        (const float4*)wih, (const float4*)whh, (const float4*)input, (const float4*)hx,
        (uint4*)p_wih, (uint4*)p_whh, (uint4*)p_in, (uint4*)p_hx);

    gx_kernel<<<1, 512>>>(G, gxo);

    dim3 grid1(FH / TN, B / TM, NN);   // (16, 4, 21)
    gates_gemm<<<grid1, 512, SM_BYTES>>>(bhh, ntypes);

    dim3 grid2(HH / 256, B);           // (4, 512)
    pass2<<<grid2, 128>>>(cx, tptr, hy, cy);
}